// round 12
// baseline (speedup 1.0000x reference)
#include <cuda_runtime.h>
#include <cstdint>

// SplineActivation: y[b,w] = clamped cubic B-spline (16 uniform knots on [-3,3],
// degree 3) of x[b,w], per-channel coefficients coefs[w, 0..17].
//
// Round-12: seven designs pinned at ~2TB/s HBM; the shared property was
// channel-tiled CTAs reading 512B slices of each 4KB row (DRAM row-buffer
// thrash across ~600 interleaved streams). This round removes tiling: each CTA
// owns FULL 4KB rows in 32KB contiguous chunks. Table for all 1024 channels
// must fit in smem -> uniform control-point form (18 CP/channel = 72KB,
// pre-divided by 6), SoA-permuted so the 4 scalar-LDS gather is conflict-free
// for any per-lane interval; segment basis cubics computed in registers.

#define W_TOTAL  1024
#define B_TOTAL  8192
#define N_CTRL   18
#define NB_IV    15
#define BD       512
#define NCTA     296           // 2 CTAs per SM on 148 SMs
#define CROWS    8             // rows per chunk (32KB contiguous)
#define N_CHUNKS (B_TOTAL / CROWS)   // 1024

// Control points, permuted slot layout, pre-divided by 6:
// g_P[i*1024 + slot(c)],  slot(c) = (c&3)*256 + (c>>2).
__device__ float g_P[N_CTRL * W_TOTAL];

// ---------------------------------------------------------------------------
// Build: threads 0..71 of each block compute the 18x4 weight matrix W[i][j]
// (FP32 port of the R2 blossom construction: interval cubic in u from unit
// coefficient responses, Newton divided differences -> monomial, blossom at
// integer args). Then each thread emits one control point. Grid 72 x 256.
// ---------------------------------------------------------------------------
__global__ __launch_bounds__(256)
void build_cp_kernel(const float* __restrict__ coefs) {
    __shared__ float W[N_CTRL * 4];
    const int t = threadIdx.x;

    if (t < N_CTRL * 4) {
        const int i = t >> 2;                 // control point index 0..17
        const int j = t & 3;                  // local coef index 0..3
        int k = i - 2; if (k < 0) k = 0; if (k > 14) k = 14;

        float tk[22];
#pragma unroll
        for (int m = 0; m < 16; m++)
            tk[3 + m] = (float)(-3.0 + (double)m * (6.0 / 15.0));
        tk[0] = tk[1] = tk[2] = tk[3];
        tk[19] = tk[20] = tk[21] = tk[18];

        const int   kg    = k + 3;
        const float x0    = tk[kg];
        const float delta = (tk[kg + 1] - tk[kg]) * (1.0f / 3.0f);
        const float Kev   = fmaf((float)k, 0.4f, -3.0f);  // eval origin

        float uu[4], ff[4];
#pragma unroll
        for (int m = 0; m < 4; m++) {
            float x = x0 + delta * (float)m;
            uu[m] = (x - Kev) * 2.5f;
            float left[3], right[3];
#pragma unroll
            for (int i2 = 1; i2 <= 3; i2++) {
                left [i2 - 1] = x - tk[kg + 1 - i2];
                right[i2 - 1] = tk[kg + i2] - x;
            }
            float N[4];
            N[0] = 1.0f;
#pragma unroll
            for (int jj = 1; jj <= 3; jj++) {
                float saved = 0.0f;
#pragma unroll
                for (int r = 0; r < jj; r++) {
                    float temp = N[r] / (right[r] + left[jj - 1 - r]);
                    N[r] = saved + right[r] * temp;
                    saved = left[jj - 1 - r] * temp;
                }
                N[jj] = saved;
            }
            ff[m] = N[j];                     // unit-coefficient response
        }

        // General divided differences in u.
        float d1[3], d2[2], d3;
#pragma unroll
        for (int m = 0; m < 3; m++) d1[m] = (ff[m+1] - ff[m]) / (uu[m+1] - uu[m]);
#pragma unroll
        for (int m = 0; m < 2; m++) d2[m] = (d1[m+1] - d1[m]) / (uu[m+2] - uu[m]);
        d3 = (d2[1] - d2[0]) / (uu[3] - uu[0]);

        // Newton -> monomial b0..b3 (in u).
        float b0, b1, b2, b3;
        b1 = d3;            b0 = d2[0] - d3 * uu[2];
        b2 = b1; b1 = b0 - b1 * uu[1]; b0 = d1[0] - b0 * uu[1];
        b3 = b2; b2 = b1 - b2 * uu[0]; b1 = b0 - b1 * uu[0]; b0 = ff[0] - b0 * uu[0];

        // Blossom at integer args (i-k-2, i-k-1, i-k).
        const float ja = (float)(i - k) - 2.0f, jb = ja + 1.0f, jc = ja + 2.0f;
        const float e1 = ja + jb + jc;
        const float e2 = ja * jb + ja * jc + jb * jc;
        const float e3 = ja * jb * jc;
        const float P  = b0 + b1 * e1 * (1.0f / 3.0f)
                            + b2 * e2 * (1.0f / 3.0f) + b3 * e3;

        W[t] = P * (1.0f / 6.0f);             // fold the global 1/6
    }
    __syncthreads();

    const int idx = blockIdx.x * 256 + t;     // 0..18431
    const int c   = idx & (W_TOTAL - 1);
    const int i   = idx >> 10;
    int k = i - 2; if (k < 0) k = 0; if (k > 14) k = 14;

    float acc = 0.0f;
#pragma unroll
    for (int j = 0; j < 4; j++)
        acc = fmaf(__ldg(&coefs[c * N_CTRL + k + j]), W[i * 4 + j], acc);

    const int slot = (c & 3) * 256 + (c >> 2);
    g_P[i * W_TOTAL + slot] = acc;
}

// ---------------------------------------------------------------------------
// Eval. 512 threads/CTA, 296 CTAs (2/SM). vcol = t&255 owns channels
// 4*vcol..+3 (one float4 of X/Y per row); rsub = t>>8. Chunk = 8 full rows,
// 32KB contiguous DRAM per chunk. Gather: 4 scalar LDS at word
// k*1024 + e*256 + vcol -> lanes = consecutive vcol -> 32 distinct banks for
// any per-lane k. Basis cubics (x6) in registers; CPs pre-divided by 6.
// ---------------------------------------------------------------------------
__device__ __forceinline__ float eval_cp(float x, const float* __restrict__ p) {
    float fi = floorf(fmaf(x, 2.5f, 7.5f));
    fi       = fminf(fmaxf(fi, 0.0f), 14.0f);
    const int kk = (int)fi;
    const float u = (x - fmaf(fi, 0.4f, -3.0f)) * 2.5f;

    const float v  = 1.0f - u;
    const float u2 = u * u;
    const float B0 = v * v * v;                               // 6*U0
    const float B3 = u2 * u;                                  // 6*U3
    const float B1 = fmaf(u2, fmaf(3.0f, u, -6.0f), 4.0f);    // 6*U1
    const float B2 = fmaf(fmaf(fmaf(-3.0f, u, 3.0f), u, 3.0f), u, 1.0f); // 6*U2

    const float* pk = p + (kk << 10);
    float y = B0 * pk[0];
    y = fmaf(B1, pk[1 * W_TOTAL], y);
    y = fmaf(B2, pk[2 * W_TOTAL], y);
    y = fmaf(B3, pk[3 * W_TOTAL], y);
    return y;
}

__global__ __launch_bounds__(BD, 2)
void spline_eval_kernel(const float* __restrict__ X, float* __restrict__ Y) {
    extern __shared__ __align__(16) float sp[];   // 73,728 B

    const int t = threadIdx.x;
    {
        const float4* g4 = (const float4*)g_P;
        float4*       s4 = (float4*)sp;
#pragma unroll
        for (int i = 0; i < (N_CTRL * W_TOTAL / 4) / BD; i++)
            s4[i * BD + t] = g4[i * BD + t];
    }
    __syncthreads();

    const int vcol = t & 255;
    const int rsub = t >> 8;                 // 0..1
    const float* tab0 = sp + vcol;           // e=0; e adds 256
    const float* tab1 = sp + 256 + vcol;
    const float* tab2 = sp + 512 + vcol;
    const float* tab3 = sp + 768 + vcol;

    const float4* Xv = (const float4*)X;
    float4*       Yv = (float4*)Y;
    const int vrow = W_TOTAL / 4;            // 256 float4 per row

    for (int chunk = blockIdx.x; chunk < N_CHUNKS; chunk += gridDim.x) {
        const int r0 = chunk * CROWS + rsub; // rows r0, r0+2, r0+4, r0+6

        float4 xv[4];
#pragma unroll
        for (int q = 0; q < 4; q++)
            xv[q] = Xv[(size_t)(r0 + 2 * q) * vrow + vcol];

#pragma unroll
        for (int q = 0; q < 4; q++) {
            float4 r;
            r.x = eval_cp(xv[q].x, tab0);
            r.y = eval_cp(xv[q].y, tab1);
            r.z = eval_cp(xv[q].z, tab2);
            r.w = eval_cp(xv[q].w, tab3);
            xv[q] = r;
        }

#pragma unroll
        for (int q = 0; q < 4; q++)
            Yv[(size_t)(r0 + 2 * q) * vrow + vcol] = xv[q];
    }
}

// ---------------------------------------------------------------------------
extern "C" void kernel_launch(void* const* d_in, const int* in_sizes, int n_in,
                              void* d_out, int out_size) {
    const float* X     = (const float*)d_in[0];
    const float* coefs = (const float*)d_in[1];
    if (n_in >= 2 && in_sizes[0] < in_sizes[1]) {   // identify by size
        X     = (const float*)d_in[1];
        coefs = (const float*)d_in[0];
    }
    float* Y = (float*)d_out;

    build_cp_kernel<<<N_CTRL * W_TOTAL / 256, 256>>>(coefs);  // 72 x 256

    const int smem_bytes = N_CTRL * W_TOTAL * (int)sizeof(float);  // 73,728
    cudaFuncSetAttribute(spline_eval_kernel,
                         cudaFuncAttributeMaxDynamicSharedMemorySize, smem_bytes);

    spline_eval_kernel<<<NCTA, BD, smem_bytes>>>(X, Y);
}

// round 13
// speedup vs baseline: 1.0755x; 1.0755x over previous
#include <cuda_runtime.h>
#include <cstdint>

// SplineActivation: y[b,w] = clamped cubic B-spline (16 uniform knots on [-3,3],
// degree 3) of x[b,w], per-channel coefficients coefs[w, 0..17].
//
// Round-13: eight designs pinned at 16.8-17.3us eval regardless of MLP,
// occupancy, load path (LDG/cp.async), store path (STG/TMA), vector width, or
// DRAM contiguity -> the eval loop sits on the effective DRAM byte wall for
// 32MB in + 32MB out. The only recoverable time is the 0.7us build-kernel +
// launch-gap tax. This round fuses the table build into the eval kernel:
//  * main loop BYTE-IDENTICAL to the proven R6 structure (no cache hints,
//    no in-loop barriers, R=8 unroll, conflict-free LDS.128 gather);
//  * first iteration's 8 LDGs peeled ABOVE the prologue so the ~400-cycle
//    matrix+table build hides under first-tile DRAM latency;
//  * coefs read directly via __ldg (72KB, L2-resident).

#define W_TOTAL  1024
#define B_TOTAL  8192
#define NB_IV    15
#define CH       128
#define BD       256
#define R        8            // rows per thread per iteration (16 rows/CTA-iter)
#define N_CTRL   18
#define GY       92           // 8 x 92 = 736 CTAs ~= 5 per SM

__global__ __launch_bounds__(BD, 5)
void spline_fused_kernel(const float* __restrict__ X,
                         const float* __restrict__ coefs,
                         float* __restrict__ Y) {
    __shared__ float4 sp[NB_IV][CH];         // 30,720 B  poly tile
    __shared__ float4 M[NB_IV * 4];          //    960 B  conversion cubics

    const int t  = threadIdx.x;
    const int c0 = blockIdx.x * CH;
    const int ch = t & (CH - 1);
    const int rl = t >> 7;                   // 0..1
    const int rstep = gridDim.y * 2 * R;

    // ---- Peel: issue the first tile's 8 independent LDGs immediately. ----
    const int base0 = blockIdx.y * 2 * R;
    const int r00   = base0 + rl * R;
    const float* xp0 = X + (size_t)r00 * W_TOTAL + c0 + ch;
    float xv0[R];
#pragma unroll
    for (int q = 0; q < R; q++) xv0[q] = xp0[q * W_TOTAL];

    // ---- Prologue A: threads 0..59 compute the 15x4 conversion cubics. ----
    if (t < NB_IV * 4) {
        const int k = t >> 2;
        const int j = t & 3;

        float tk[22];
#pragma unroll
        for (int m = 0; m < 16; m++)
            tk[3 + m] = (float)(-3.0 + (double)m * (6.0 / 15.0));
        tk[0] = tk[1] = tk[2] = tk[3];
        tk[19] = tk[20] = tk[21] = tk[18];

        const int   kg    = k + 3;
        const float x0    = tk[kg];
        const float delta = (tk[kg + 1] - tk[kg]) * (1.0f / 3.0f);
        const float Kev   = fmaf((float)k, 0.4f, -3.0f);

        float f[4];
#pragma unroll
        for (int m = 0; m < 4; m++) {
            float x = x0 + delta * (float)m;
            float left[3], right[3];
#pragma unroll
            for (int i2 = 1; i2 <= 3; i2++) {
                left [i2 - 1] = x - tk[kg + 1 - i2];
                right[i2 - 1] = tk[kg + i2] - x;
            }
            float N[4];
            N[0] = 1.0f;
#pragma unroll
            for (int jj = 1; jj <= 3; jj++) {
                float saved = 0.0f;
#pragma unroll
                for (int r = 0; r < jj; r++) {
                    float temp = N[r] / (right[r] + left[jj - 1 - r]);
                    N[r] = saved + right[r] * temp;
                    saved = left[jj - 1 - r] * temp;
                }
                N[jj] = saved;
            }
            f[m] = N[j];
        }

        const float id = 1.0f / delta;
        const float d1 = (f[1] - f[0]) * id;
        const float d2 = (f[2] - 2.0f * f[1] + f[0]) * (0.5f * id * id);
        const float d3 = (f[3] - 3.0f * f[2] + 3.0f * f[1] - f[0])
                         * ((1.0f / 6.0f) * id * id * id);
        const float a0 = f[0];
        const float a1 = d1 - delta * d2 + 2.0f * delta * delta * d3;
        const float a2 = d2 - 3.0f * delta * d3;
        const float a3 = d3;

        const float s0 = x0 - Kev;
        const float b3 = a3;
        const float b2 = a2 - 3.0f * a3 * s0;
        const float b1 = a1 - 2.0f * a2 * s0 + 3.0f * a3 * s0 * s0;
        const float b0 = a0 - a1 * s0 + a2 * s0 * s0 - a3 * s0 * s0 * s0;

        M[t] = make_float4(b0, b1, b2, b3);
    }
    __syncthreads();

    // ---- Prologue B: build this CTA's poly tile (7.5 entries/thread). ----
    for (int i = t; i < NB_IV * CH; i += BD) {
        const int k   = i >> 7;
        const int chl = i & (CH - 1);
        const float* cf = coefs + (size_t)(c0 + chl) * N_CTRL + k;
        float4 acc = make_float4(0.f, 0.f, 0.f, 0.f);
#pragma unroll
        for (int j = 0; j < 4; j++) {
            float  c = __ldg(&cf[j]);
            float4 m = M[k * 4 + j];
            acc.x = fmaf(c, m.x, acc.x);
            acc.y = fmaf(c, m.y, acc.y);
            acc.z = fmaf(c, m.z, acc.z);
            acc.w = fmaf(c, m.w, acc.w);
        }
        sp[k][chl] = acc;
    }
    __syncthreads();

    // ---- Peeled first iteration (loads already in registers). ----
    {
        float* yp = Y + (size_t)r00 * W_TOTAL + c0 + ch;
#pragma unroll
        for (int q = 0; q < R; q++) {
            float x  = xv0[q];
            float fi = floorf(fmaf(x, 2.5f, 7.5f));
            fi       = fminf(fmaxf(fi, 0.0f), 14.0f);
            int   k  = (int)fi;
            float s  = x - fmaf(fi, 0.4f, -3.0f);
            float4 p = sp[k][ch];
            xv0[q] = fmaf(fmaf(fmaf(p.w, s, p.z), s, p.y), s, p.x);
        }
#pragma unroll
        for (int q = 0; q < R; q++) yp[q * W_TOTAL] = xv0[q];
    }

    // ---- Main loop: identical structure to R6 (proven floor). ----
    for (int base = base0 + rstep; base < B_TOTAL; base += rstep) {
        const int r0 = base + rl * R;
        const float* xp = X + (size_t)r0 * W_TOTAL + c0 + ch;
        float*       yp = Y + (size_t)r0 * W_TOTAL + c0 + ch;

        float xv[R];
#pragma unroll
        for (int q = 0; q < R; q++) xv[q] = xp[q * W_TOTAL];

#pragma unroll
        for (int q = 0; q < R; q++) {
            float x  = xv[q];
            float fi = floorf(fmaf(x, 2.5f, 7.5f));
            fi       = fminf(fmaxf(fi, 0.0f), 14.0f);
            int   k  = (int)fi;
            float s  = x - fmaf(fi, 0.4f, -3.0f);
            float4 p = sp[k][ch];
            xv[q] = fmaf(fmaf(fmaf(p.w, s, p.z), s, p.y), s, p.x);
        }

#pragma unroll
        for (int q = 0; q < R; q++) yp[q * W_TOTAL] = xv[q];
    }
}

// ---------------------------------------------------------------------------
extern "C" void kernel_launch(void* const* d_in, const int* in_sizes, int n_in,
                              void* d_out, int out_size) {
    const float* X     = (const float*)d_in[0];
    const float* coefs = (const float*)d_in[1];
    if (n_in >= 2 && in_sizes[0] < in_sizes[1]) {   // identify by size
        X     = (const float*)d_in[1];
        coefs = (const float*)d_in[0];
    }
    float* Y = (float*)d_out;

    dim3 grid(W_TOTAL / CH, GY);             // 8 x 92 = 736 CTAs ~= 5 per SM
    spline_fused_kernel<<<grid, BD>>>(X, coefs, Y);
}

// round 15
// speedup vs baseline: 1.2094x; 1.1245x over previous
#include <cuda_runtime.h>
#include <cstdint>
#include <cmath>

// SplineActivation: y[b,w] = clamped cubic B-spline (16 uniform knots on [-3,3],
// degree 3) of x[b,w], per-channel coefficients coefs[w, 0..17].
//
// Round-15 (= round-14 resubmit after infra failure): eval = R6 verbatim
// (eight designs proved 16.77us is the effective DRAM duplex wall:
// 64MB / ~3.8TB/s). The remaining tax (build kernel + gap, ~0.7us) is shrunk
// by moving the input-independent 15x4 interval-conversion matrix to HOST
// FP64 at capture time (deterministic, graph-legal: it bakes into the 960B
// kernel parameter block). The device build kernel is then just 4 coef loads
// + 16 FMA + 1 STG.128 per thread — no divisions, no smem, no barrier.
// Bonus: FP64-exact M -> rel_err ~4e-7.

#define W_TOTAL  1024
#define B_TOTAL  8192
#define NB_IV    15
#define CH       128
#define BD       256
#define R        8            // rows per thread per iteration
#define N_CTRL   18
#define GY       92           // 8 x 92 = 736 CTAs ~= 5 per SM

__device__ float4 g_poly[NB_IV * W_TOTAL];   // [interval][channel] monomial cubic

struct MMat { float4 m[NB_IV * 4]; };        // 960 B kernel parameter

// ---------------------------------------------------------------------------
// Build: one g_poly entry per thread; M comes in via the parameter block
// (constant bank). Grid 60 x 256. No divisions, no smem, no barriers.
// ---------------------------------------------------------------------------
__global__ __launch_bounds__(BD)
void build_poly_kernel(const float* __restrict__ coefs, const MMat M) {
    const int idx = blockIdx.x * BD + threadIdx.x;   // 0..15359
    const int c   = idx & (W_TOTAL - 1);
    const int k   = idx >> 10;

    float4 acc = make_float4(0.f, 0.f, 0.f, 0.f);
#pragma unroll
    for (int j = 0; j < 4; j++) {
        float  cf = __ldg(&coefs[c * N_CTRL + k + j]);
        float4 m  = M.m[k * 4 + j];
        acc.x = fmaf(cf, m.x, acc.x);
        acc.y = fmaf(cf, m.y, acc.y);
        acc.z = fmaf(cf, m.z, acc.z);
        acc.w = fmaf(cf, m.w, acc.w);
    }
    g_poly[k * W_TOTAL + c] = acc;
}

// ---------------------------------------------------------------------------
// Hot kernel: R6 verbatim (proven floor). 256 threads over a 128-channel
// tile: ch = t&127, rl = t>>7; R=8 row unroll (16 rows/CTA-iteration).
// smem sp[k][128] float4: k-stride 2048B, lane stride 16B -> conflict-free
// LDS.128 for any per-lane interval mix. Grid 8 x 92 = 736 CTAs.
// ---------------------------------------------------------------------------
__global__ __launch_bounds__(BD, 5)
void spline_eval_kernel(const float* __restrict__ X, float* __restrict__ Y) {
    __shared__ float4 sp[NB_IV][CH];         // 30,720 B
    const int t  = threadIdx.x;
    const int c0 = blockIdx.x * CH;

    for (int i = t; i < NB_IV * CH; i += BD)
        ((float4*)sp)[i] = g_poly[(i >> 7) * W_TOTAL + c0 + (i & (CH - 1))];
    __syncthreads();

    const int ch = t & (CH - 1);
    const int rl = t >> 7;                   // 0..1
    const int rstep = gridDim.y * 2 * R;

    for (int base = blockIdx.y * 2 * R; base < B_TOTAL; base += rstep) {
        const int r0 = base + rl * R;        // this thread: rows r0 .. r0+7
        const float* xp = X + (size_t)r0 * W_TOTAL + c0 + ch;
        float*       yp = Y + (size_t)r0 * W_TOTAL + c0 + ch;

        float xv[R];
#pragma unroll
        for (int q = 0; q < R; q++) xv[q] = xp[q * W_TOTAL];

#pragma unroll
        for (int q = 0; q < R; q++) {
            float x  = xv[q];
            float fi = floorf(fmaf(x, 2.5f, 7.5f));
            fi       = fminf(fmaxf(fi, 0.0f), 14.0f);
            int   k  = (int)fi;
            float s  = x - fmaf(fi, 0.4f, -3.0f);
            float4 p = sp[k][ch];
            xv[q] = fmaf(fmaf(fmaf(p.w, s, p.z), s, p.y), s, p.x);
        }

#pragma unroll
        for (int q = 0; q < R; q++) yp[q * W_TOTAL] = xv[q];
    }
}

// ---------------------------------------------------------------------------
// Host-side FP64 computation of the conversion matrix (input-independent;
// runs at graph-capture time, bakes into the kernel parameter block).
// Entry (k,j): monomial cubic in s = x - Kev(k) of basis N_{k+j} on interval
// k, via Cox-de Boor sampled at 4 points + uniform divided differences.
// ---------------------------------------------------------------------------
static void compute_M_host(MMat* out) {
    double t[22];
    for (int m = 0; m < 16; m++) {
        double kd = -3.0 + (double)m * (6.0 / 15.0);   // numpy linspace
        t[3 + m] = (double)(float)kd;                  // reference's f32 cast
    }
    t[0] = t[1] = t[2] = t[3];
    t[19] = t[20] = t[21] = t[18];

    for (int k = 0; k < NB_IV; k++) {
        const int kg = k + 3;
        const double x0    = t[kg];
        const double delta = (t[kg + 1] - t[kg]) / 3.0;
        // Must match the eval kernel's interval origin bit-exactly:
        // fi*0.4f - 3.0f via fp32 fma.
        const double Kev   = (double)fmaf((float)k, 0.4f, -3.0f);

        for (int j = 0; j < 4; j++) {
            double f[4];
            for (int m = 0; m < 4; m++) {
                double x = x0 + delta * (double)m;
                double left[3], right[3];
                for (int i2 = 1; i2 <= 3; i2++) {
                    left [i2 - 1] = x - t[kg + 1 - i2];
                    right[i2 - 1] = t[kg + i2] - x;
                }
                double N[4];
                N[0] = 1.0;
                for (int jj = 1; jj <= 3; jj++) {
                    double saved = 0.0;
                    for (int r = 0; r < jj; r++) {
                        double temp = N[r] / (right[r] + left[jj - 1 - r]);
                        N[r] = saved + right[r] * temp;
                        saved = left[jj - 1 - r] * temp;
                    }
                    N[jj] = saved;
                }
                f[m] = N[j];
            }

            const double d1 = (f[1] - f[0]) / delta;
            const double d2 = (f[2] - 2.0 * f[1] + f[0]) / (2.0 * delta * delta);
            const double d3 = (f[3] - 3.0 * f[2] + 3.0 * f[1] - f[0])
                              / (6.0 * delta * delta * delta);
            const double a0 = f[0];
            const double a1 = d1 - delta * d2 + 2.0 * delta * delta * d3;
            const double a2 = d2 - 3.0 * delta * d3;
            const double a3 = d3;

            const double s0 = x0 - Kev;
            const double b3 = a3;
            const double b2 = a2 - 3.0 * a3 * s0;
            const double b1 = a1 - 2.0 * a2 * s0 + 3.0 * a3 * s0 * s0;
            const double b0 = a0 - a1 * s0 + a2 * s0 * s0 - a3 * s0 * s0 * s0;

            out->m[k * 4 + j] = make_float4((float)b0, (float)b1,
                                            (float)b2, (float)b3);
        }
    }
}

// ---------------------------------------------------------------------------
extern "C" void kernel_launch(void* const* d_in, const int* in_sizes, int n_in,
                              void* d_out, int out_size) {
    const float* X     = (const float*)d_in[0];
    const float* coefs = (const float*)d_in[1];
    if (n_in >= 2 && in_sizes[0] < in_sizes[1]) {   // identify by size
        X     = (const float*)d_in[1];
        coefs = (const float*)d_in[0];
    }
    float* Y = (float*)d_out;

    MMat M;
    compute_M_host(&M);      // input-independent, deterministic, capture-time

    build_poly_kernel<<<NB_IV * W_TOTAL / BD, BD>>>(coefs, M);   // 60 x 256

    dim3 grid(W_TOTAL / CH, GY);             // 8 x 92 = 736 CTAs ~= 5 per SM
    spline_eval_kernel<<<grid, BD>>>(X, Y);
}

// round 16
// speedup vs baseline: 1.2495x; 1.0331x over previous
#include <cuda_runtime.h>
#include <cstdint>
#include <cmath>

// SplineActivation: y[b,w] = clamped cubic B-spline (16 uniform knots on [-3,3],
// degree 3) of x[b,w], per-channel coefficients coefs[w, 0..17].
//
// Round-16: R15 (16.96us) + Programmatic Dependent Launch. Eval is at its
// ~16.6us DRAM-path floor (nine designs triangulated it); the remaining
// 0.32us is build-kernel + launch serialization. PDL lets the eval grid
// launch while the build kernel drains: build fires
// cudaTriggerProgrammaticLaunchCompletion() at its end; eval gates its first
// g_poly read behind cudaGridDependencySynchronize(). Everything else is
// byte-identical to R15 (host-FP64 conversion matrix baked into the build
// kernel's 960B parameter block; proven R6 eval loop).

#define W_TOTAL  1024
#define B_TOTAL  8192
#define NB_IV    15
#define CH       128
#define BD       256
#define R        8            // rows per thread per iteration
#define N_CTRL   18
#define GY       92           // 8 x 92 = 736 CTAs ~= 5 per SM

__device__ float4 g_poly[NB_IV * W_TOTAL];   // [interval][channel] monomial cubic

struct MMat { float4 m[NB_IV * 4]; };        // 960 B kernel parameter

// ---------------------------------------------------------------------------
// Build: one g_poly entry per thread; M arrives via the parameter block.
// Grid 60 x 256. No divisions, no smem, no barriers. Fires the PDL trigger
// so the dependent eval grid can begin launching.
// ---------------------------------------------------------------------------
__global__ __launch_bounds__(BD)
void build_poly_kernel(const float* __restrict__ coefs, const MMat M) {
    const int idx = blockIdx.x * BD + threadIdx.x;   // 0..15359
    const int c   = idx & (W_TOTAL - 1);
    const int k   = idx >> 10;

    float4 acc = make_float4(0.f, 0.f, 0.f, 0.f);
#pragma unroll
    for (int j = 0; j < 4; j++) {
        float  cf = __ldg(&coefs[c * N_CTRL + k + j]);
        float4 m  = M.m[k * 4 + j];
        acc.x = fmaf(cf, m.x, acc.x);
        acc.y = fmaf(cf, m.y, acc.y);
        acc.z = fmaf(cf, m.z, acc.z);
        acc.w = fmaf(cf, m.w, acc.w);
    }
    g_poly[k * W_TOTAL + c] = acc;

#if __CUDA_ARCH__ >= 900
    cudaTriggerProgrammaticLaunchCompletion();
#endif
}

// ---------------------------------------------------------------------------
// Hot kernel: R6/R15 verbatim, plus the PDL dependency gate before the first
// g_poly read. 256 threads over a 128-channel tile: ch = t&127, rl = t>>7;
// R=8 row unroll. smem sp[k][128] float4: k-stride 2048B, lane stride 16B ->
// conflict-free LDS.128 for any per-lane interval mix. Grid 8 x 92 = 736.
// ---------------------------------------------------------------------------
__global__ __launch_bounds__(BD, 5)
void spline_eval_kernel(const float* __restrict__ X, float* __restrict__ Y) {
    __shared__ float4 sp[NB_IV][CH];         // 30,720 B
    const int t  = threadIdx.x;
    const int c0 = blockIdx.x * CH;

#if __CUDA_ARCH__ >= 900
    cudaGridDependencySynchronize();         // build kernel's writes visible
#endif

    for (int i = t; i < NB_IV * CH; i += BD)
        ((float4*)sp)[i] = g_poly[(i >> 7) * W_TOTAL + c0 + (i & (CH - 1))];
    __syncthreads();

    const int ch = t & (CH - 1);
    const int rl = t >> 7;                   // 0..1
    const int rstep = gridDim.y * 2 * R;

    for (int base = blockIdx.y * 2 * R; base < B_TOTAL; base += rstep) {
        const int r0 = base + rl * R;        // this thread: rows r0 .. r0+7
        const float* xp = X + (size_t)r0 * W_TOTAL + c0 + ch;
        float*       yp = Y + (size_t)r0 * W_TOTAL + c0 + ch;

        float xv[R];
#pragma unroll
        for (int q = 0; q < R; q++) xv[q] = xp[q * W_TOTAL];

#pragma unroll
        for (int q = 0; q < R; q++) {
            float x  = xv[q];
            float fi = floorf(fmaf(x, 2.5f, 7.5f));
            fi       = fminf(fmaxf(fi, 0.0f), 14.0f);
            int   k  = (int)fi;
            float s  = x - fmaf(fi, 0.4f, -3.0f);
            float4 p = sp[k][ch];
            xv[q] = fmaf(fmaf(fmaf(p.w, s, p.z), s, p.y), s, p.x);
        }

#pragma unroll
        for (int q = 0; q < R; q++) yp[q * W_TOTAL] = xv[q];
    }
}

// ---------------------------------------------------------------------------
// Host-side FP64 conversion matrix (input-independent, capture-time).
// Entry (k,j): monomial cubic in s = x - Kev(k) of basis N_{k+j} on interval
// k, via Cox-de Boor sampled at 4 points + uniform divided differences.
// ---------------------------------------------------------------------------
static void compute_M_host(MMat* out) {
    double t[22];
    for (int m = 0; m < 16; m++) {
        double kd = -3.0 + (double)m * (6.0 / 15.0);   // numpy linspace
        t[3 + m] = (double)(float)kd;                  // reference's f32 cast
    }
    t[0] = t[1] = t[2] = t[3];
    t[19] = t[20] = t[21] = t[18];

    for (int k = 0; k < NB_IV; k++) {
        const int kg = k + 3;
        const double x0    = t[kg];
        const double delta = (t[kg + 1] - t[kg]) / 3.0;
        // Must match the eval kernel's interval origin bit-exactly:
        const double Kev   = (double)fmaf((float)k, 0.4f, -3.0f);

        for (int j = 0; j < 4; j++) {
            double f[4];
            for (int m = 0; m < 4; m++) {
                double x = x0 + delta * (double)m;
                double left[3], right[3];
                for (int i2 = 1; i2 <= 3; i2++) {
                    left [i2 - 1] = x - t[kg + 1 - i2];
                    right[i2 - 1] = t[kg + i2] - x;
                }
                double N[4];
                N[0] = 1.0;
                for (int jj = 1; jj <= 3; jj++) {
                    double saved = 0.0;
                    for (int r = 0; r < jj; r++) {
                        double temp = N[r] / (right[r] + left[jj - 1 - r]);
                        N[r] = saved + right[r] * temp;
                        saved = left[jj - 1 - r] * temp;
                    }
                    N[jj] = saved;
                }
                f[m] = N[j];
            }

            const double d1 = (f[1] - f[0]) / delta;
            const double d2 = (f[2] - 2.0 * f[1] + f[0]) / (2.0 * delta * delta);
            const double d3 = (f[3] - 3.0 * f[2] + 3.0 * f[1] - f[0])
                              / (6.0 * delta * delta * delta);
            const double a0 = f[0];
            const double a1 = d1 - delta * d2 + 2.0 * delta * delta * d3;
            const double a2 = d2 - 3.0 * delta * d3;
            const double a3 = d3;

            const double s0 = x0 - Kev;
            const double b3 = a3;
            const double b2 = a2 - 3.0 * a3 * s0;
            const double b1 = a1 - 2.0 * a2 * s0 + 3.0 * a3 * s0 * s0;
            const double b0 = a0 - a1 * s0 + a2 * s0 * s0 - a3 * s0 * s0 * s0;

            out->m[k * 4 + j] = make_float4((float)b0, (float)b1,
                                            (float)b2, (float)b3);
        }
    }
}

// ---------------------------------------------------------------------------
extern "C" void kernel_launch(void* const* d_in, const int* in_sizes, int n_in,
                              void* d_out, int out_size) {
    const float* X     = (const float*)d_in[0];
    const float* coefs = (const float*)d_in[1];
    if (n_in >= 2 && in_sizes[0] < in_sizes[1]) {   // identify by size
        X     = (const float*)d_in[1];
        coefs = (const float*)d_in[0];
    }
    float* Y = (float*)d_out;

    MMat M;
    compute_M_host(&M);      // input-independent, deterministic, capture-time

    build_poly_kernel<<<NB_IV * W_TOTAL / BD, BD>>>(coefs, M);   // 60 x 256

    // Eval launched with PDL: may begin launching while build drains.
    cudaLaunchConfig_t cfg = {};
    cfg.gridDim  = dim3(W_TOTAL / CH, GY);   // 8 x 92 = 736 CTAs
    cfg.blockDim = dim3(BD);
    cfg.stream   = 0;
    cudaLaunchAttribute attr[1];
    attr[0].id = cudaLaunchAttributeProgrammaticStreamSerialization;
    attr[0].val.programmaticStreamSerializationAllowed = 1;
    cfg.attrs    = attr;
    cfg.numAttrs = 1;
    cudaLaunchKernelEx(&cfg, spline_eval_kernel, X, Y);
}

// round 17
// speedup vs baseline: 1.2520x; 1.0020x over previous
#include <cuda_runtime.h>
#include <cstdint>
#include <cmath>

// SplineActivation: y[b,w] = clamped cubic B-spline (16 uniform knots on [-3,3],
// degree 3) of x[b,w], per-channel coefficients coefs[w, 0..17].
//
// Round-17 = Round-16 confirmation (rigor.md: re-bench before claiming a win).
// Final form:
//  * Math: per-(interval,channel) monomial cubic table (exact C^2 spline ->
//    piecewise cubic identity), built by a 60x256 device kernel applying a
//    HOST-FP64 15x4 conversion matrix (input-independent, computed at graph
//    capture time, passed in the 960B kernel parameter block).
//  * Eval: proven R6 loop — 128-channel tiles, conflict-free LDS.128 gather
//    (k-stride 2048B, lane stride 16B), R=8 row unroll, coalesced LDG/STG,
//    grid 8x92, no in-loop barriers.
//  * PDL: eval grid launches while the build kernel drains; first g_poly read
//    gated by cudaGridDependencySynchronize().
// Measured: 16.416us total, rel_err 1.1e-7 — 64MB mandatory traffic at
// ~3.9TB/s effective DRAM duplex (the wall, triangulated by nine designs).

#define W_TOTAL  1024
#define B_TOTAL  8192
#define NB_IV    15
#define CH       128
#define BD       256
#define R        8            // rows per thread per iteration
#define N_CTRL   18
#define GY       92           // 8 x 92 = 736 CTAs ~= 5 per SM

__device__ float4 g_poly[NB_IV * W_TOTAL];   // [interval][channel] monomial cubic

struct MMat { float4 m[NB_IV * 4]; };        // 960 B kernel parameter

// ---------------------------------------------------------------------------
// Build: one g_poly entry per thread; M arrives via the parameter block.
// Grid 60 x 256. No divisions, no smem, no barriers. Fires the PDL trigger.
// ---------------------------------------------------------------------------
__global__ __launch_bounds__(BD)
void build_poly_kernel(const float* __restrict__ coefs, const MMat M) {
    const int idx = blockIdx.x * BD + threadIdx.x;   // 0..15359
    const int c   = idx & (W_TOTAL - 1);
    const int k   = idx >> 10;

    float4 acc = make_float4(0.f, 0.f, 0.f, 0.f);
#pragma unroll
    for (int j = 0; j < 4; j++) {
        float  cf = __ldg(&coefs[c * N_CTRL + k + j]);
        float4 m  = M.m[k * 4 + j];
        acc.x = fmaf(cf, m.x, acc.x);
        acc.y = fmaf(cf, m.y, acc.y);
        acc.z = fmaf(cf, m.z, acc.z);
        acc.w = fmaf(cf, m.w, acc.w);
    }
    g_poly[k * W_TOTAL + c] = acc;

#if __CUDA_ARCH__ >= 900
    cudaTriggerProgrammaticLaunchCompletion();
#endif
}

// ---------------------------------------------------------------------------
// Hot kernel: proven R6 loop + PDL gate. 256 threads over a 128-channel tile:
// ch = t&127, rl = t>>7; R=8 row unroll (16 rows/CTA-iteration).
// smem sp[k][128] float4: k-stride 2048B, lane stride 16B -> conflict-free
// LDS.128 for any per-lane interval mix. Grid 8 x 92 = 736 CTAs.
// ---------------------------------------------------------------------------
__global__ __launch_bounds__(BD, 5)
void spline_eval_kernel(const float* __restrict__ X, float* __restrict__ Y) {
    __shared__ float4 sp[NB_IV][CH];         // 30,720 B
    const int t  = threadIdx.x;
    const int c0 = blockIdx.x * CH;

#if __CUDA_ARCH__ >= 900
    cudaGridDependencySynchronize();         // build kernel's writes visible
#endif

    for (int i = t; i < NB_IV * CH; i += BD)
        ((float4*)sp)[i] = g_poly[(i >> 7) * W_TOTAL + c0 + (i & (CH - 1))];
    __syncthreads();

    const int ch = t & (CH - 1);
    const int rl = t >> 7;                   // 0..1
    const int rstep = gridDim.y * 2 * R;

    for (int base = blockIdx.y * 2 * R; base < B_TOTAL; base += rstep) {
        const int r0 = base + rl * R;        // this thread: rows r0 .. r0+7
        const float* xp = X + (size_t)r0 * W_TOTAL + c0 + ch;
        float*       yp = Y + (size_t)r0 * W_TOTAL + c0 + ch;

        float xv[R];
#pragma unroll
        for (int q = 0; q < R; q++) xv[q] = xp[q * W_TOTAL];

#pragma unroll
        for (int q = 0; q < R; q++) {
            float x  = xv[q];
            float fi = floorf(fmaf(x, 2.5f, 7.5f));
            fi       = fminf(fmaxf(fi, 0.0f), 14.0f);
            int   k  = (int)fi;
            float s  = x - fmaf(fi, 0.4f, -3.0f);
            float4 p = sp[k][ch];
            xv[q] = fmaf(fmaf(fmaf(p.w, s, p.z), s, p.y), s, p.x);
        }

#pragma unroll
        for (int q = 0; q < R; q++) yp[q * W_TOTAL] = xv[q];
    }
}

// ---------------------------------------------------------------------------
// Host-side FP64 conversion matrix (input-independent, capture-time).
// Entry (k,j): monomial cubic in s = x - Kev(k) of basis N_{k+j} on interval
// k, via Cox-de Boor sampled at 4 points + uniform divided differences.
// ---------------------------------------------------------------------------
static void compute_M_host(MMat* out) {
    double t[22];
    for (int m = 0; m < 16; m++) {
        double kd = -3.0 + (double)m * (6.0 / 15.0);   // numpy linspace
        t[3 + m] = (double)(float)kd;                  // reference's f32 cast
    }
    t[0] = t[1] = t[2] = t[3];
    t[19] = t[20] = t[21] = t[18];

    for (int k = 0; k < NB_IV; k++) {
        const int kg = k + 3;
        const double x0    = t[kg];
        const double delta = (t[kg + 1] - t[kg]) / 3.0;
        // Must match the eval kernel's interval origin bit-exactly:
        const double Kev   = (double)fmaf((float)k, 0.4f, -3.0f);

        for (int j = 0; j < 4; j++) {
            double f[4];
            for (int m = 0; m < 4; m++) {
                double x = x0 + delta * (double)m;
                double left[3], right[3];
                for (int i2 = 1; i2 <= 3; i2++) {
                    left [i2 - 1] = x - t[kg + 1 - i2];
                    right[i2 - 1] = t[kg + i2] - x;
                }
                double N[4];
                N[0] = 1.0;
                for (int jj = 1; jj <= 3; jj++) {
                    double saved = 0.0;
                    for (int r = 0; r < jj; r++) {
                        double temp = N[r] / (right[r] + left[jj - 1 - r]);
                        N[r] = saved + right[r] * temp;
                        saved = left[jj - 1 - r] * temp;
                    }
                    N[jj] = saved;
                }
                f[m] = N[j];
            }

            const double d1 = (f[1] - f[0]) / delta;
            const double d2 = (f[2] - 2.0 * f[1] + f[0]) / (2.0 * delta * delta);
            const double d3 = (f[3] - 3.0 * f[2] + 3.0 * f[1] - f[0])
                              / (6.0 * delta * delta * delta);
            const double a0 = f[0];
            const double a1 = d1 - delta * d2 + 2.0 * delta * delta * d3;
            const double a2 = d2 - 3.0 * delta * d3;
            const double a3 = d3;

            const double s0 = x0 - Kev;
            const double b3 = a3;
            const double b2 = a2 - 3.0 * a3 * s0;
            const double b1 = a1 - 2.0 * a2 * s0 + 3.0 * a3 * s0 * s0;
            const double b0 = a0 - a1 * s0 + a2 * s0 * s0 - a3 * s0 * s0 * s0;

            out->m[k * 4 + j] = make_float4((float)b0, (float)b1,
                                            (float)b2, (float)b3);
        }
    }
}

// ---------------------------------------------------------------------------
extern "C" void kernel_launch(void* const* d_in, const int* in_sizes, int n_in,
                              void* d_out, int out_size) {
    const float* X     = (const float*)d_in[0];
    const float* coefs = (const float*)d_in[1];
    if (n_in >= 2 && in_sizes[0] < in_sizes[1]) {   // identify by size
        X     = (const float*)d_in[1];
        coefs = (const float*)d_in[0];
    }
    float* Y = (float*)d_out;

    MMat M;
    compute_M_host(&M);      // input-independent, deterministic, capture-time

    build_poly_kernel<<<NB_IV * W_TOTAL / BD, BD>>>(coefs, M);   // 60 x 256

    // Eval launched with PDL: begins launching while build drains.
    cudaLaunchConfig_t cfg = {};
    cfg.gridDim  = dim3(W_TOTAL / CH, GY);   // 8 x 92 = 736 CTAs
    cfg.blockDim = dim3(BD);
    cfg.stream   = 0;
    cudaLaunchAttribute attr[1];
    attr[0].id = cudaLaunchAttributeProgrammaticStreamSerialization;
    attr[0].val.programmaticStreamSerializationAllowed = 1;
    cfg.attrs    = attr;
    cfg.numAttrs = 1;
    cudaLaunchKernelEx(&cfg, spline_eval_kernel, X, Y);
}